// round 11
// baseline (speedup 1.0000x reference)
#include <cuda_runtime.h>
#include <cuda.h>
#include <cstdint>

static constexpr int DIM   = 8;
static constexpr int PATCH = 16;
static constexpr int NPAIR = PATCH - 1;
static constexpr int W     = 2 * DIM;

__device__ __forceinline__ unsigned long long pack2(float lo, float hi) {
    unsigned long long r;
    asm("mov.b64 %0, {%1, %2};" : "=l"(r) : "f"(lo), "f"(hi));
    return r;
}
__device__ __forceinline__ unsigned long long fma2(unsigned long long a,
                                                   unsigned long long b,
                                                   unsigned long long c) {
    unsigned long long d;
    asm("fma.rn.f32x2 %0, %1, %2, %3;" : "=l"(d) : "l"(a), "l"(b), "l"(c));
    return d;
}
__device__ __forceinline__ uint32_t smem_u32(const void* p) {
    uint32_t a;
    asm("{ .reg .u64 t; cvta.to.shared.u64 t, %1; cvt.u32.u64 %0, t; }"
        : "=r"(a) : "l"(p));
    return a;
}

// One signature cell (a,b) per thread; both a<8 and b<8 are warp-uniform.
// v[j] = (S3[a][b][2j], S3[a][b][2j+1]); lead coef drives j=0..3 (c<8),
// lag coef drives j=4..7 (c>=8), both against the same packed delta pairs.
template <bool AHI, bool BHI>   // AHI: a>=8, BHI: b>=8
__device__ __forceinline__ void mainloop(
    const float (*__restrict__ sd)[DIM],
    int al, int bl,
    float& s1, float& s2,
    unsigned long long* __restrict__ v)
{
    #pragma unroll
    for (int k = 0; k < NPAIR; k++) {
        const ulonglong2* sdv = reinterpret_cast<const ulonglong2*>(sd[k]);
        const ulonglong2 dA = sdv[0];
        const ulonglong2 dB = sdv[1];
        const float da = sd[k][al];
        const float db = sd[k][bl];

        float coefL, coefG;
        if (!AHI && !BHI) {
            // both active in LEAD; lag trivial.
            float tt = da * db;
            float pa = s1 * db;
            coefL = fmaf(0.5f, pa, s2);
            coefL = fmaf(1.0f / 6.0f, tt, coefL);
            s2    = s2 + pa;
            s2    = fmaf(0.5f, tt, s2);
            s1   += da;
            coefG = s2;
        } else if (!AHI && BHI) {
            // a active in LEAD, b active in LAG (uses updated s1).
            coefL = s2;
            s1   += da;
            float pa = s1 * db;
            coefG = fmaf(0.5f, pa, s2);
            s2   += pa;
        } else if (AHI && !BHI) {
            // b active in LEAD (pre-update s1), a active in LAG.
            float pa = s1 * db;
            coefL = fmaf(0.5f, pa, s2);
            s2   += pa;
            coefG = s2;
            s1   += da;
        } else {
            // both active in LAG; lead trivial.
            coefL = s2;
            float tt = da * db;
            float pa = s1 * db;        // pre-lag-step s1
            coefG = fmaf(0.5f, pa, s2);
            coefG = fmaf(1.0f / 6.0f, tt, coefG);
            s2   += pa;
            s2    = fmaf(0.5f, tt, s2);
            s1   += da;
        }

        const unsigned long long cL = pack2(coefL, coefL);
        const unsigned long long cG = pack2(coefG, coefG);

        v[0] = fma2(cL, dA.x, v[0]);  v[1] = fma2(cL, dA.y, v[1]);
        v[2] = fma2(cL, dB.x, v[2]);  v[3] = fma2(cL, dB.y, v[3]);
        v[4] = fma2(cG, dA.x, v[4]);  v[5] = fma2(cG, dA.y, v[5]);
        v[6] = fma2(cG, dB.x, v[6]);  v[7] = fma2(cG, dB.y, v[7]);
    }
}

// 16B-chunk swizzle == TMA SW128 layout for a 128B-wide tile.
__device__ __forceinline__ int swz(int c) {
    return c ^ ((c >> 3) & 7);
}

__global__ __launch_bounds__(256, 6)
void leadlag_sig_kernel(const float* __restrict__ x,
                        float* __restrict__ out,
                        int seq_len,
                        const __grid_constant__ CUtensorMap dmap)
{
    const int i = blockIdx.x;
    const int t = threadIdx.x;       // 0..255
    // t = (a_hi<<7) | (b_hi<<6) | (a_lo<<3) | b_lo  — halves warp-uniform
    const int a_hi = (t >> 7) & 1;
    const int b_hi = (t >> 6) & 1;
    const int al   = (t >> 3) & 7;   // a_lo
    const int bl   = t & 7;          // b_lo
    const int a    = a_hi * 8 + al;
    const int b    = b_hi * 8 + bl;

    __shared__ __align__(16)   float sd[NPAIR][DIM];
    __shared__ __align__(1024) ulonglong2 sbuf[1024];   // 16 KB SW128 tile

    if (t < NPAIR * DIM) {
        int k  = t >> 3;
        int c  = t & 7;
        int g1 = i + k - (PATCH - 2);
        int g0 = i + k - (PATCH - 1);
        float v1 = (g1 >= 0) ? x[g1 * DIM + c] : 0.0f;
        float v0 = (g0 >= 0) ? x[g0 * DIM + c] : 0.0f;
        sd[k][c] = v1 - v0;
    }
    __syncthreads();

    float s1 = 0.0f, s2 = 0.0f;
    unsigned long long v[8];
    #pragma unroll
    for (int j = 0; j < 8; j++) v[j] = 0ull;

    if      (!a_hi && !b_hi) mainloop<false, false>(sd, al, bl, s1, s2, v);
    else if (!a_hi &&  b_hi) mainloop<false, true >(sd, al, bl, s1, s2, v);
    else if ( a_hi && !b_hi) mainloop<true , false>(sd, al, bl, s1, s2, v);
    else                     mainloop<true , true >(sd, al, bl, s1, s2, v);

    // ---- stage level-3 row into SW128-swizzled smem ----
    {
        const int r = a * W + b;
        #pragma unroll
        for (int s = 0; s < 4; s++)
            sbuf[swz(4 * r + s)] = make_ulonglong2(v[2 * s], v[2 * s + 1]);
    }

    // ---- level-1 / level-2 outputs ----
    float* out1 = out;
    float* out2 = out + (size_t)seq_len * W;

    if (b == 0) out1[(size_t)i * W + a] = s1;
    out2[(size_t)i * (W * W) + a * W + b] = s2;

    __syncthreads();

    // ---- level-3: single TMA tensor store (SW128 smem -> linear gmem) ----
    if (t == 0) {
        asm volatile("fence.proxy.async.shared::cta;" ::: "memory");
        uint32_t sa = smem_u32(sbuf);
        asm volatile(
            "cp.async.bulk.tensor.3d.global.shared::cta.tile.bulk_group "
            "[%0, {%1, %2, %3}], [%4];"
            :: "l"(&dmap), "r"(0), "r"(0), "r"(i), "r"(sa)
            : "memory");
        asm volatile("cp.async.bulk.commit_group;" ::: "memory");
        asm volatile("cp.async.bulk.wait_group 0;" ::: "memory");
    }
}

extern "C" void kernel_launch(void* const* d_in, const int* in_sizes, int n_in,
                              void* d_out, int out_size)
{
    const float* x   = (const float*)d_in[0];
    float*       out = (float*)d_out;
    const int seq_len = in_sizes[0] / DIM;   // 8192

    // L3 region: seq_len tiles of 128 rows x 32 f32 (128B wide), contiguous.
    float* out3 = out + (size_t)seq_len * (W + W * W);

    typedef CUresult (*EncodeFn)(
        CUtensorMap*, CUtensorMapDataType, cuuint32_t, void*,
        const cuuint64_t*, const cuuint64_t*, const cuuint32_t*,
        const cuuint32_t*, CUtensorMapInterleave, CUtensorMapSwizzle,
        CUtensorMapL2promotion, CUtensorMapFloatOOBfill);
    static EncodeFn encode = nullptr;
    if (!encode) {
        cudaDriverEntryPointQueryResult st;
        void* fn = nullptr;
        cudaGetDriverEntryPoint("cuTensorMapEncodeTiled", &fn,
                                cudaEnableDefault, &st);
        encode = (EncodeFn)fn;
    }

    CUtensorMap dmap;
    cuuint64_t dims[3]    = {32, 128, (cuuint64_t)seq_len};
    cuuint64_t strides[2] = {128, 16384};          // bytes
    cuuint32_t box[3]     = {32, 128, 1};
    cuuint32_t estr[3]    = {1, 1, 1};
    encode(&dmap, CU_TENSOR_MAP_DATA_TYPE_FLOAT32, 3, (void*)out3,
           dims, strides, box, estr,
           CU_TENSOR_MAP_INTERLEAVE_NONE, CU_TENSOR_MAP_SWIZZLE_128B,
           CU_TENSOR_MAP_L2_PROMOTION_L2_128B,
           CU_TENSOR_MAP_FLOAT_OOB_FILL_NONE);

    leadlag_sig_kernel<<<seq_len, 256>>>(x, out, seq_len, dmap);
}